// round 7
// baseline (speedup 1.0000x reference)
#include <cuda_runtime.h>
#include <cuda_fp16.h>
#include <math.h>
#include <stdint.h>

#define B_ 2048
#define F_ 128
#define U_ 1024
#define V_ 512
#define C_ 10

#define BT_ 128            // batch rows per CTA (M)
#define VT_ 128            // v cols per CTA (N)
#define KC_ 64             // k per chunk (4 k16-steps)
#define NCHUNK (U_ / KC_)  // 16
#define STAGES 6

// ---------------- global scratch ----------------
__device__ float g_logits[B_ * C_];
__device__ float g_bsum[C_];
// W1 as fp16 fragment quads: per (f,ch): [pr=16][v=512] uint2,
// pr = s*4 + t -> k-quad (base+2t, base+2t+1, base+2t+8, base+2t+9), base = ch*64+s*16
__device__ uint2 g_W1H[(size_t)F_ * NCHUNK * 16 * 512];

// ---------------- helpers ----------------
__device__ __forceinline__ uint32_t smem_u32(const void* p) {
    uint32_t a;
    asm("{ .reg .u64 t; cvta.to.shared.u64 t, %1; cvt.u32.u64 %0, t; }" : "=r"(a) : "l"(p));
    return a;
}
__device__ __forceinline__ void cpa16(uint32_t dst, const void* src) {
    asm volatile("cp.async.cg.shared.global [%0], [%1], 16;" :: "r"(dst), "l"(src));
}
#define CP_COMMIT() asm volatile("cp.async.commit_group;")
#define CP_WAIT(n)  asm volatile("cp.async.wait_group %0;" :: "n"(n))

__device__ __forceinline__ uint32_t pack_h2(float a, float b) {
    __half2 h = __floats2half2_rn(a, b);
    return *(uint32_t*)&h;
}
__device__ __forceinline__ uint32_t h2u(__half2 h) { return *(uint32_t*)&h; }

__device__ __forceinline__ void mma_f16(float* d, uint32_t a0, uint32_t a1, uint32_t a2,
                                        uint32_t a3, uint32_t b0, uint32_t b1) {
    asm volatile(
        "mma.sync.aligned.m16n8k16.row.col.f32.f16.f16.f32 "
        "{%0,%1,%2,%3}, {%4,%5,%6,%7}, {%8,%9}, {%0,%1,%2,%3};"
        : "+f"(d[0]), "+f"(d[1]), "+f"(d[2]), "+f"(d[3])
        : "r"(a0), "r"(a1), "r"(a2), "r"(a3), "r"(b0), "r"(b1));
}

// ---------------- smem layout (floats) ----------------
#define STAGE_U2 (16 * VT_)                  // 2048 uint2 per stage (16KB)
#define STAGES_F (STAGES * STAGE_U2 * 2)     // 24576 floats
#define EWS2_OFF STAGES_F
#define XS_OFF   (EWS2_OFF + 512)
#define B1S_OFF  (XS_OFF + BT_)
#define W2S_OFF  (B1S_OFF + VT_)
#define SMEM_FLOATS (W2S_OFF + VT_ * 12)
#define SMEM_BYTES  (SMEM_FLOATS * 4)        // ~107 KB -> 2 CTAs/SM

// ---------------------------------------------------------------------------
// Prep: W1 [F,U,V] fp32 -> g_W1H fp16 fragment quads.
// ---------------------------------------------------------------------------
__global__ void __launch_bounds__(256)
nam_prep_kernel(const float* __restrict__ W1) {
    const int ch = blockIdx.x, f = blockIdx.y;
    const int tid = threadIdx.x;
    const float* src = W1 + (size_t)f * U_ * V_;
    uint2* dst = g_W1H + ((size_t)f * NCHUNK + ch) * (16 * 512);

    #pragma unroll
    for (int r = 0; r < 32; r++) {
        int idx = r * 256 + tid;
        int pr = idx >> 9;
        int v  = idx & 511;
        int s  = pr >> 2, t = pr & 3;
        int ka = ch * KC_ + s * 16 + 2 * t;
        uint2 o;
        o.x = pack_h2(src[(size_t)ka * V_ + v],       src[(size_t)(ka + 1) * V_ + v]);
        o.y = pack_h2(src[(size_t)(ka + 8) * V_ + v], src[(size_t)(ka + 9) * V_ + v]);
        dst[idx] = o;
    }
}

// ---------------------------------------------------------------------------
__global__ void nam_init_kernel(const float* __restrict__ b2,
                                const float* __restrict__ b_out) {
    int t = blockIdx.x * blockDim.x + threadIdx.x;
    if (t < B_ * C_) g_logits[t] = 0.0f;
    if (t < C_) {
        float s = b_out[t];
        for (int f = 0; f < F_; f++) s += b2[f * C_ + t];
        g_bsum[t] = s;
    }
}

__global__ void nam_dummy_kernel() {}

// ---------------------------------------------------------------------------
// Main GEMM (fp16 mma, in-place B/E register prefetch).
// Grid (16, 4, 128), 256 thr, 8 warps (4 M x 2 N), warp tile 32x64. 2 CTAs/SM.
// ---------------------------------------------------------------------------
__global__ void __launch_bounds__(256, 2)
nam_gemm_kernel(const float* __restrict__ x,
                const float* __restrict__ exu_w,
                const float* __restrict__ exu_b,
                const float* __restrict__ b1,
                const float* __restrict__ W2) {
    extern __shared__ float sm[];
    uint2*   Bs   = (uint2*)sm;
    __half2* ews2 = (__half2*)(sm + EWS2_OFF);
    float*   xs   = sm + XS_OFF;
    float*   b1s  = sm + B1S_OFF;
    float*   W2s  = sm + W2S_OFF;
    float*   s_part = sm;

    const int f  = blockIdx.z;
    const int b0 = blockIdx.x * BT_;
    const int v0 = blockIdx.y * VT_;
    const int tid = threadIdx.x;
    const int wid = tid >> 5;
    const int lane = tid & 31;
    const int g = lane >> 2;
    const int t = lane & 3;
    const int m0  = (wid & 3) * 32;
    const int nwp = wid >> 2;
    const int n0  = nwp * 64;

    const uint32_t smem_base = smem_u32(sm);
    const uint2* W1f = g_W1H + ((size_t)f * NCHUNK) * (16 * 512) + v0;

    // prologue: first STAGES-1 = 5 chunk loads
    #pragma unroll
    for (int pc = 0; pc < STAGES - 1; pc++) {
        #pragma unroll
        for (int it = 0; it < 4; it++) {
            int i = tid + it * 256;
            int pr = i >> 6;
            int vv2 = (i & 63) * 2;
            int tpr = pr & 3;
            int swz2 = (tpr << 3) ^ ((tpr >> 1) << 2);
            uint32_t dst2 = pc * STAGE_U2 + pr * VT_ + (vv2 ^ swz2);
            cpa16(smem_base + dst2 * 8u, W1f + (size_t)pc * (16 * 512) + pr * 512 + vv2);
        }
        CP_COMMIT();
    }

    const float eb = exu_b[f];
    for (int i = tid; i < U_ / 2; i += 256) {
        float2 w = *(const float2*)&exu_w[f * U_ + 2 * i];
        ews2[i] = __floats2half2_rn(expf(w.x), expf(w.y));
    }
    if (tid < BT_) {
        xs[tid]  = x[(size_t)(b0 + tid) * F_ + f] - eb;
        b1s[tid] = b1[(size_t)f * V_ + v0 + tid];
    }
    for (int i = tid; i < VT_ * C_; i += 256) {
        int v = i / C_, c = i - v * C_;
        W2s[v * 12 + c] = W2[(size_t)f * V_ * C_ + (size_t)(v0 + v) * C_ + c];
    }
    __syncthreads();

    __half2 xh[2][2];
    #pragma unroll
    for (int mt = 0; mt < 2; mt++) {
        xh[mt][0] = __half2half2(__float2half_rn(xs[m0 + mt * 16 + g]));
        xh[mt][1] = __half2half2(__float2half_rn(xs[m0 + mt * 16 + g + 8]));
    }

    float acc[2][8][4];
    #pragma unroll
    for (int mt = 0; mt < 2; mt++)
        #pragma unroll
        for (int nt = 0; nt < 8; nt++)
            #pragma unroll
            for (int c = 0; c < 4; c++) acc[mt][nt][c] = 0.0f;

    const int swz = (t << 3) ^ ((t >> 1) << 2);
    // chunk-invariant column offsets (uint2 index within a pr-row)
    int vp[8];
    #pragma unroll
    for (int nt = 0; nt < 8; nt++) vp[nt] = (n0 + nt * 8 + g) ^ swz;

    // ---------------- mainloop: 16 chunks of K=64 ----------------
    for (int ch = 0; ch < NCHUNK; ch++) {
        CP_WAIT(4);
        __syncthreads();
        const uint2* Bst = Bs + (ch % STAGES) * STAGE_U2;
        const int e2b = (ch * KC_) >> 1;

        // preload s=0 operands
        uint2 bb[8];
        #pragma unroll
        for (int nt = 0; nt < 8; nt++) bb[nt] = Bst[t * VT_ + vp[nt]];
        __half2 elo = ews2[e2b + t];
        __half2 ehi = ews2[e2b + t + 4];

        #pragma unroll
        for (int s = 0; s < 4; s++) {
            // A fragments for this s
            uint32_t a[2][4];
            #pragma unroll
            for (int mt = 0; mt < 2; mt++) {
                a[mt][0] = h2u(__hmul2_sat(xh[mt][0], elo));
                a[mt][1] = h2u(__hmul2_sat(xh[mt][1], elo));
                a[mt][2] = h2u(__hmul2_sat(xh[mt][0], ehi));
                a[mt][3] = h2u(__hmul2_sat(xh[mt][1], ehi));
            }
            // prefetch next s's E early (covered by 16 MMAs below)
            if (s < 3) {
                elo = ews2[e2b + (s + 1) * 8 + t];
                ehi = ews2[e2b + (s + 1) * 8 + t + 4];
            }
            const int prrow_next = ((s + 1) * 4 + t) * VT_;
            #pragma unroll
            for (int nt = 0; nt < 8; nt++) {
                uint2 bcur = bb[nt];
                // in-place prefetch of next s's fragment (WAR safe: issue-ordered)
                if (s < 3) bb[nt] = Bst[prrow_next + vp[nt]];
                mma_f16(acc[0][nt], a[0][0], a[0][1], a[0][2], a[0][3], bcur.x, bcur.y);
                mma_f16(acc[1][nt], a[1][0], a[1][1], a[1][2], a[1][3], bcur.x, bcur.y);
            }
        }

        int nc = ch + STAGES - 1;
        if (nc < NCHUNK) {
            #pragma unroll
            for (int it = 0; it < 4; it++) {
                int i = tid + it * 256;
                int pr = i >> 6;
                int vv2 = (i & 63) * 2;
                int tpr = pr & 3;
                int sw2 = (tpr << 3) ^ ((tpr >> 1) << 2);
                uint32_t dst2 = (nc % STAGES) * STAGE_U2 + pr * VT_ + (vv2 ^ sw2);
                cpa16(smem_base + dst2 * 8u, W1f + (size_t)nc * (16 * 512) + pr * 512 + vv2);
            }
            CP_COMMIT();
        }
    }
    __syncthreads();   // mainloop done; stage smem reusable

    // ---------------- epilogue ----------------
    #pragma unroll
    for (int mt = 0; mt < 2; mt++) {
        float p[2][10];
        #pragma unroll
        for (int i = 0; i < 2; i++)
            #pragma unroll
            for (int c = 0; c < 10; c++) p[i][c] = 0.0f;

        #pragma unroll
        for (int nt = 0; nt < 8; nt++) {
            #pragma unroll
            for (int k = 0; k < 2; k++) {
                int vl = n0 + nt * 8 + 2 * t + k;
                float b1v = b1s[vl];
                float w2[10];
                #pragma unroll
                for (int c = 0; c < 10; c++) w2[c] = W2s[vl * 12 + c];
                float h2a = fmaxf(acc[mt][nt][k] + b1v, 0.0f);
                float h2b = fmaxf(acc[mt][nt][2 + k] + b1v, 0.0f);
                #pragma unroll
                for (int c = 0; c < 10; c++) {
                    p[0][c] = fmaf(h2a, w2[c], p[0][c]);
                    p[1][c] = fmaf(h2b, w2[c], p[1][c]);
                }
            }
        }
        #pragma unroll
        for (int off = 1; off < 4; off <<= 1)
            #pragma unroll
            for (int i = 0; i < 2; i++)
                #pragma unroll
                for (int c = 0; c < 10; c++)
                    p[i][c] += __shfl_xor_sync(0xffffffffu, p[i][c], off);

        if (t == 0) {
            #pragma unroll
            for (int rh = 0; rh < 2; rh++) {
                int r = m0 + mt * 16 + g + rh * 8;
                #pragma unroll
                for (int c = 0; c < 10; c++)
                    s_part[(r * 2 + nwp) * 10 + c] = p[rh][c];
            }
        }
    }
    __syncthreads();

    for (int i = tid; i < BT_ * C_; i += 256) {
        int r = i / C_, c = i - r * C_;
        float s = s_part[(r * 2 + 0) * 10 + c] + s_part[(r * 2 + 1) * 10 + c];
        atomicAdd(&g_logits[(b0 + r) * C_ + c], s);
    }
}

// ---------------------------------------------------------------------------
__global__ void nam_softmax_kernel(float* __restrict__ out) {
    int b = blockIdx.x * blockDim.x + threadIdx.x;
    if (b >= B_) return;
    float v[C_];
    float m = -1e30f;
    #pragma unroll
    for (int c = 0; c < C_; c++) {
        v[c] = g_logits[b * C_ + c] + g_bsum[c];
        m = fmaxf(m, v[c]);
    }
    float s = 0.0f;
    #pragma unroll
    for (int c = 0; c < C_; c++) { v[c] = expf(v[c] - m); s += v[c]; }
    float inv = 1.0f / s;
    #pragma unroll
    for (int c = 0; c < C_; c++) out[b * C_ + c] = v[c] * inv;
}

// ---------------------------------------------------------------------------
extern "C" void kernel_launch(void* const* d_in, const int* in_sizes, int n_in,
                              void* d_out, int out_size) {
    const float* x     = (const float*)d_in[0];
    const float* exu_w = (const float*)d_in[1];
    const float* exu_b = (const float*)d_in[2];
    const float* W1    = (const float*)d_in[3];
    const float* b1    = (const float*)d_in[4];
    const float* W2    = (const float*)d_in[5];
    const float* b2    = (const float*)d_in[6];
    const float* b_out = (const float*)d_in[7];
    float* out = (float*)d_out;

    cudaFuncSetAttribute(nam_gemm_kernel,
                         cudaFuncAttributeMaxDynamicSharedMemorySize, SMEM_BYTES);

    dim3 gprep(NCHUNK, F_);
    nam_prep_kernel<<<gprep, 256>>>(W1);                        // launch 0
    nam_init_kernel<<<(B_ * C_ + 255) / 256, 256>>>(b2, b_out); // launch 1
    nam_dummy_kernel<<<1, 32>>>();                              // launch 2 (ncu align)

    dim3 ggemm(B_ / BT_, V_ / VT_, F_);
    nam_gemm_kernel<<<ggemm, 256, SMEM_BYTES>>>(x, exu_w, exu_b, b1, W2); // launch 3

    nam_softmax_kernel<<<(B_ + 255) / 256, 256>>>(out);         // launch 4
}

// round 8
// speedup vs baseline: 1.0498x; 1.0498x over previous
#include <cuda_runtime.h>
#include <cuda_fp16.h>
#include <math.h>
#include <stdint.h>

#define B_ 2048
#define F_ 128
#define U_ 1024
#define V_ 512
#define C_ 10

#define BT_ 128            // batch rows per CTA (M)
#define VT_ 128            // v cols per CTA (N)
#define KC_ 128            // k per chunk (8 k16-steps)
#define NCHUNK (U_ / KC_)  // 8
#define STAGES 3

// ---------------- global scratch ----------------
__device__ float g_logits[B_ * C_];
__device__ float g_bsum[C_];
// W1 as fp16 fragment quads: per (f,ch): [pr=32][v=512] uint2,
// pr = s*4 + t -> k-quad (base+2t, base+2t+1, base+2t+8, base+2t+9), base = ch*128+s*16
__device__ uint2 g_W1H[(size_t)F_ * NCHUNK * 32 * 512];

// ---------------- helpers ----------------
__device__ __forceinline__ uint32_t smem_u32(const void* p) {
    uint32_t a;
    asm("{ .reg .u64 t; cvta.to.shared.u64 t, %1; cvt.u32.u64 %0, t; }" : "=r"(a) : "l"(p));
    return a;
}
__device__ __forceinline__ void cpa16(uint32_t dst, const void* src) {
    asm volatile("cp.async.cg.shared.global [%0], [%1], 16;" :: "r"(dst), "l"(src));
}
#define CP_COMMIT() asm volatile("cp.async.commit_group;")
#define CP_WAIT(n)  asm volatile("cp.async.wait_group %0;" :: "n"(n))

__device__ __forceinline__ uint32_t pack_h2(float a, float b) {
    __half2 h = __floats2half2_rn(a, b);
    return *(uint32_t*)&h;
}
__device__ __forceinline__ uint32_t h2u(__half2 h) { return *(uint32_t*)&h; }

__device__ __forceinline__ void mma_f16(float* d, uint32_t a0, uint32_t a1, uint32_t a2,
                                        uint32_t a3, uint32_t b0, uint32_t b1) {
    asm volatile(
        "mma.sync.aligned.m16n8k16.row.col.f32.f16.f16.f32 "
        "{%0,%1,%2,%3}, {%4,%5,%6,%7}, {%8,%9}, {%0,%1,%2,%3};"
        : "+f"(d[0]), "+f"(d[1]), "+f"(d[2]), "+f"(d[3])
        : "r"(a0), "r"(a1), "r"(a2), "r"(a3), "r"(b0), "r"(b1));
}

// ---------------- smem layout (floats) ----------------
#define STAGE_U2 (32 * VT_)                  // 4096 uint2 per stage (32KB)
#define STAGES_F (STAGES * STAGE_U2 * 2)     // 24576 floats (96KB)
#define EWS2_OFF STAGES_F
#define XS_OFF   (EWS2_OFF + 512)
#define B1S_OFF  (XS_OFF + BT_)
#define W2S_OFF  (B1S_OFF + VT_)
#define SMEM_FLOATS (W2S_OFF + VT_ * 12)
#define SMEM_BYTES  (SMEM_FLOATS * 4)        // ~104.7 KB -> 2 CTAs/SM (228KB)

// ---------------------------------------------------------------------------
// Prep: W1 [F,U,V] fp32 -> g_W1H fp16 fragment quads (K=128 chunk layout).
// Grid (NCHUNK=8, F=128), 256 threads; per block 32 pr x 512 v.
// ---------------------------------------------------------------------------
__global__ void __launch_bounds__(256)
nam_prep_kernel(const float* __restrict__ W1) {
    const int ch = blockIdx.x, f = blockIdx.y;
    const int tid = threadIdx.x;
    const float* src = W1 + (size_t)f * U_ * V_;
    uint2* dst = g_W1H + ((size_t)f * NCHUNK + ch) * (32 * 512);

    #pragma unroll
    for (int r = 0; r < 64; r++) {
        int idx = r * 256 + tid;           // 0..16383
        int pr = idx >> 9;                 // 0..31
        int v  = idx & 511;
        int s  = pr >> 2, t = pr & 3;
        int ka = ch * KC_ + s * 16 + 2 * t;
        uint2 o;
        o.x = pack_h2(src[(size_t)ka * V_ + v],       src[(size_t)(ka + 1) * V_ + v]);
        o.y = pack_h2(src[(size_t)(ka + 8) * V_ + v], src[(size_t)(ka + 9) * V_ + v]);
        dst[idx] = o;
    }
}

// ---------------------------------------------------------------------------
__global__ void nam_init_kernel(const float* __restrict__ b2,
                                const float* __restrict__ b_out) {
    int t = blockIdx.x * blockDim.x + threadIdx.x;
    if (t < B_ * C_) g_logits[t] = 0.0f;
    if (t < C_) {
        float s = b_out[t];
        for (int f = 0; f < F_; f++) s += b2[f * C_ + t];
        g_bsum[t] = s;
    }
}

__global__ void nam_dummy_kernel() {}

// ---------------------------------------------------------------------------
// Main GEMM. Grid (16, 4, 128), 256 thr, 8 warps (4 M x 2 N), 2 CTAs/SM.
// K=128 chunks: 8 sync points total; cp.async issues spread across s-steps.
// ---------------------------------------------------------------------------
__global__ void __launch_bounds__(256, 2)
nam_gemm_kernel(const float* __restrict__ x,
                const float* __restrict__ exu_w,
                const float* __restrict__ exu_b,
                const float* __restrict__ b1,
                const float* __restrict__ W2) {
    extern __shared__ float sm[];
    uint2*   Bs   = (uint2*)sm;
    __half2* ews2 = (__half2*)(sm + EWS2_OFF);
    float*   xs   = sm + XS_OFF;
    float*   b1s  = sm + B1S_OFF;
    float*   W2s  = sm + W2S_OFF;
    float*   s_part = sm;

    const int f  = blockIdx.z;
    const int b0 = blockIdx.x * BT_;
    const int v0 = blockIdx.y * VT_;
    const int tid = threadIdx.x;
    const int wid = tid >> 5;
    const int lane = tid & 31;
    const int g = lane >> 2;
    const int t = lane & 3;
    const int m0  = (wid & 3) * 32;
    const int nwp = wid >> 2;
    const int n0  = nwp * 64;

    const uint32_t smem_base = smem_u32(sm);
    const uint2* W1f = g_W1H + ((size_t)f * NCHUNK) * (32 * 512) + v0;

    // prologue: load first STAGES-1 = 2 chunks (32KB each = 2048 x 16B)
    #pragma unroll
    for (int pc = 0; pc < STAGES - 1; pc++) {
        #pragma unroll
        for (int it = 0; it < 8; it++) {
            int i = tid + it * 256;               // 0..2047
            int pr = i >> 6;                      // 0..31
            int vv2 = (i & 63) * 2;
            int tpr = pr & 3;
            int swz2 = (tpr << 3) ^ ((tpr >> 1) << 2);
            uint32_t dst2 = pc * STAGE_U2 + pr * VT_ + (vv2 ^ swz2);
            cpa16(smem_base + dst2 * 8u, W1f + (size_t)pc * (32 * 512) + pr * 512 + vv2);
        }
        CP_COMMIT();
    }

    const float eb = exu_b[f];
    for (int i = tid; i < U_ / 2; i += 256) {
        float2 w = *(const float2*)&exu_w[f * U_ + 2 * i];
        ews2[i] = __floats2half2_rn(expf(w.x), expf(w.y));
    }
    if (tid < BT_) {
        xs[tid]  = x[(size_t)(b0 + tid) * F_ + f] - eb;
        b1s[tid] = b1[(size_t)f * V_ + v0 + tid];
    }
    for (int i = tid; i < VT_ * C_; i += 256) {
        int v = i / C_, c = i - v * C_;
        W2s[v * 12 + c] = W2[(size_t)f * V_ * C_ + (size_t)(v0 + v) * C_ + c];
    }
    __syncthreads();

    __half2 xh[2][2];
    #pragma unroll
    for (int mt = 0; mt < 2; mt++) {
        xh[mt][0] = __half2half2(__float2half_rn(xs[m0 + mt * 16 + g]));
        xh[mt][1] = __half2half2(__float2half_rn(xs[m0 + mt * 16 + g + 8]));
    }

    float acc[2][8][4];
    #pragma unroll
    for (int mt = 0; mt < 2; mt++)
        #pragma unroll
        for (int nt = 0; nt < 8; nt++)
            #pragma unroll
            for (int c = 0; c < 4; c++) acc[mt][nt][c] = 0.0f;

    const int swz = (t << 3) ^ ((t >> 1) << 2);
    int vp[8];
    #pragma unroll
    for (int nt = 0; nt < 8; nt++) vp[nt] = (n0 + nt * 8 + g) ^ swz;

    // ---------------- mainloop: 8 chunks of K=128 ----------------
    for (int ch = 0; ch < NCHUNK; ch++) {
        CP_WAIT(1);
        __syncthreads();
        const uint2* Bst = Bs + (ch % STAGES) * STAGE_U2;
        const int e2b = ch * (KC_ / 2);

        const int nc = ch + STAGES - 1;
        const bool do_load = (nc < NCHUNK);
        const uint32_t ld_stage = (nc % STAGES) * STAGE_U2;
        const uint2* ld_src = W1f + (size_t)(do_load ? nc : 0) * (32 * 512);

        // preload s=0 operands
        uint2 bb[8];
        #pragma unroll
        for (int nt = 0; nt < 8; nt++) bb[nt] = Bst[t * VT_ + vp[nt]];
        __half2 elo = ews2[e2b + t];
        __half2 ehi = ews2[e2b + t + 4];

        #pragma unroll
        for (int s = 0; s < 8; s++) {
            // one cp.async slice per s-step (8 total = full next chunk)
            if (do_load) {
                int i = tid + s * 256;
                int pr = i >> 6;
                int vv2 = (i & 63) * 2;
                int tpr = pr & 3;
                int sw2 = (tpr << 3) ^ ((tpr >> 1) << 2);
                uint32_t dst2 = ld_stage + pr * VT_ + (vv2 ^ sw2);
                cpa16(smem_base + dst2 * 8u, ld_src + pr * 512 + vv2);
            }

            uint32_t a[2][4];
            #pragma unroll
            for (int mt = 0; mt < 2; mt++) {
                a[mt][0] = h2u(__hmul2_sat(xh[mt][0], elo));
                a[mt][1] = h2u(__hmul2_sat(xh[mt][1], elo));
                a[mt][2] = h2u(__hmul2_sat(xh[mt][0], ehi));
                a[mt][3] = h2u(__hmul2_sat(xh[mt][1], ehi));
            }
            if (s < 7) {
                elo = ews2[e2b + (s + 1) * 8 + t];
                ehi = ews2[e2b + (s + 1) * 8 + t + 4];
            }
            const int prrow_next = ((s + 1) * 4 + t) * VT_;
            #pragma unroll
            for (int nt = 0; nt < 8; nt++) {
                uint2 bcur = bb[nt];
                if (s < 7) bb[nt] = Bst[prrow_next + vp[nt]];
                mma_f16(acc[0][nt], a[0][0], a[0][1], a[0][2], a[0][3], bcur.x, bcur.y);
                mma_f16(acc[1][nt], a[1][0], a[1][1], a[1][2], a[1][3], bcur.x, bcur.y);
            }
        }
        CP_COMMIT();
    }
    __syncthreads();   // mainloop done; stage smem reusable

    // ---------------- epilogue ----------------
    #pragma unroll
    for (int mt = 0; mt < 2; mt++) {
        float p[2][10];
        #pragma unroll
        for (int i = 0; i < 2; i++)
            #pragma unroll
            for (int c = 0; c < 10; c++) p[i][c] = 0.0f;

        #pragma unroll
        for (int nt = 0; nt < 8; nt++) {
            #pragma unroll
            for (int k = 0; k < 2; k++) {
                int vl = n0 + nt * 8 + 2 * t + k;
                float b1v = b1s[vl];
                float w2[10];
                #pragma unroll
                for (int c = 0; c < 10; c++) w2[c] = W2s[vl * 12 + c];
                float h2a = fmaxf(acc[mt][nt][k] + b1v, 0.0f);
                float h2b = fmaxf(acc[mt][nt][2 + k] + b1v, 0.0f);
                #pragma unroll
                for (int c = 0; c < 10; c++) {
                    p[0][c] = fmaf(h2a, w2[c], p[0][c]);
                    p[1][c] = fmaf(h2b, w2[c], p[1][c]);
                }
            }
        }
        #pragma unroll
        for (int off = 1; off < 4; off <<= 1)
            #pragma unroll
            for (int i = 0; i < 2; i++)
                #pragma unroll
                for (int c = 0; c < 10; c++)
                    p[i][c] += __shfl_xor_sync(0xffffffffu, p[i][c], off);

        if (t == 0) {
            #pragma unroll
            for (int rh = 0; rh < 2; rh++) {
                int r = m0 + mt * 16 + g + rh * 8;
                #pragma unroll
                for (int c = 0; c < 10; c++)
                    s_part[(r * 2 + nwp) * 10 + c] = p[rh][c];
            }
        }
    }
    __syncthreads();

    for (int i = tid; i < BT_ * C_; i += 256) {
        int r = i / C_, c = i - r * C_;
        float s = s_part[(r * 2 + 0) * 10 + c] + s_part[(r * 2 + 1) * 10 + c];
        atomicAdd(&g_logits[(b0 + r) * C_ + c], s);
    }
}

// ---------------------------------------------------------------------------
__global__ void nam_softmax_kernel(float* __restrict__ out) {
    int b = blockIdx.x * blockDim.x + threadIdx.x;
    if (b >= B_) return;
    float v[C_];
    float m = -1e30f;
    #pragma unroll
    for (int c = 0; c < C_; c++) {
        v[c] = g_logits[b * C_ + c] + g_bsum[c];
        m = fmaxf(m, v[c]);
    }
    float s = 0.0f;
    #pragma unroll
    for (int c = 0; c < C_; c++) { v[c] = expf(v[c] - m); s += v[c]; }
    float inv = 1.0f / s;
    #pragma unroll
    for (int c = 0; c < C_; c++) out[b * C_ + c] = v[c] * inv;
}

// ---------------------------------------------------------------------------
extern "C" void kernel_launch(void* const* d_in, const int* in_sizes, int n_in,
                              void* d_out, int out_size) {
    const float* x     = (const float*)d_in[0];
    const float* exu_w = (const float*)d_in[1];
    const float* exu_b = (const float*)d_in[2];
    const float* W1    = (const float*)d_in[3];
    const float* b1    = (const float*)d_in[4];
    const float* W2    = (const float*)d_in[5];
    const float* b2    = (const float*)d_in[6];
    const float* b_out = (const float*)d_in[7];
    float* out = (float*)d_out;

    cudaFuncSetAttribute(nam_gemm_kernel,
                         cudaFuncAttributeMaxDynamicSharedMemorySize, SMEM_BYTES);

    dim3 gprep(NCHUNK, F_);
    nam_prep_kernel<<<gprep, 256>>>(W1);                        // launch 0
    nam_init_kernel<<<(B_ * C_ + 255) / 256, 256>>>(b2, b_out); // launch 1
    nam_dummy_kernel<<<1, 32>>>();                              // launch 2 (ncu align)

    dim3 ggemm(B_ / BT_, V_ / VT_, F_);
    nam_gemm_kernel<<<ggemm, 256, SMEM_BYTES>>>(x, exu_w, exu_b, b1, W2); // launch 3

    nam_softmax_kernel<<<(B_ + 255) / 256, 256>>>(out);         // launch 4
}

// round 9
// speedup vs baseline: 1.0787x; 1.0276x over previous
#include <cuda_runtime.h>
#include <cuda_fp16.h>
#include <math.h>
#include <stdint.h>

#define B_ 2048
#define F_ 128
#define U_ 1024
#define V_ 512
#define C_ 10

#define BT_ 128            // batch rows per CTA (M)
#define VT_ 128            // v cols per CTA (N)
#define KC_ 128            // k per chunk (8 k16-steps)
#define NCHUNK (U_ / KC_)  // 8
#define STAGES 3

// ---------------- global scratch ----------------
__device__ float g_logits[B_ * C_];
__device__ float g_bsum[C_];
// W1 as fp16 fragment quads: per (f,ch): [pr=32][v=512] uint2,
// pr = s*4 + t -> k-quad (base+2t, base+2t+1, base+2t+8, base+2t+9), base = ch*128+s*16
__device__ uint2 g_W1H[(size_t)F_ * NCHUNK * 32 * 512];

// ---------------- helpers ----------------
__device__ __forceinline__ uint32_t smem_u32(const void* p) {
    uint32_t a;
    asm("{ .reg .u64 t; cvta.to.shared.u64 t, %1; cvt.u32.u64 %0, t; }" : "=r"(a) : "l"(p));
    return a;
}
__device__ __forceinline__ void cpa16(uint32_t dst, const void* src) {
    asm volatile("cp.async.cg.shared.global [%0], [%1], 16;" :: "r"(dst), "l"(src));
}
#define CP_COMMIT() asm volatile("cp.async.commit_group;")
#define CP_WAIT(n)  asm volatile("cp.async.wait_group %0;" :: "n"(n))
#define BARG(id)    asm volatile("bar.sync %0, 128;" :: "r"(id) : "memory")

__device__ __forceinline__ uint32_t pack_h2(float a, float b) {
    __half2 h = __floats2half2_rn(a, b);
    return *(uint32_t*)&h;
}
__device__ __forceinline__ uint32_t h2u(__half2 h) { return *(uint32_t*)&h; }

__device__ __forceinline__ void mma_f16(float* d, uint32_t a0, uint32_t a1, uint32_t a2,
                                        uint32_t a3, uint32_t b0, uint32_t b1) {
    asm volatile(
        "mma.sync.aligned.m16n8k16.row.col.f32.f16.f16.f32 "
        "{%0,%1,%2,%3}, {%4,%5,%6,%7}, {%8,%9}, {%0,%1,%2,%3};"
        : "+f"(d[0]), "+f"(d[1]), "+f"(d[2]), "+f"(d[3])
        : "r"(a0), "r"(a1), "r"(a2), "r"(a3), "r"(b0), "r"(b1));
}

// ---------------- smem layout (floats) ----------------
#define STAGE_U2 (32 * VT_)                  // 4096 uint2 per stage (32KB)
#define STAGES_F (STAGES * STAGE_U2 * 2)     // 24576 floats (96KB)
#define EWS2_OFF STAGES_F
#define XS_OFF   (EWS2_OFF + 512)
#define B1S_OFF  (XS_OFF + BT_)
#define W2S_OFF  (B1S_OFF + VT_)
#define SMEM_FLOATS (W2S_OFF + VT_ * 12)
#define SMEM_BYTES  (SMEM_FLOATS * 4)        // ~104.7 KB -> 2 CTAs/SM

// ---------------------------------------------------------------------------
// Prep: W1 fp32 -> g_W1H fp16 fragment quads; also zero logits & build bsum.
// Grid (NCHUNK=8, F=128), 256 threads.
// ---------------------------------------------------------------------------
__global__ void __launch_bounds__(256)
nam_prep_kernel(const float* __restrict__ W1,
                const float* __restrict__ b2,
                const float* __restrict__ b_out) {
    const int ch = blockIdx.x, f = blockIdx.y;
    const int tid = threadIdx.x;

    // merged init: blocks with ch==0 zero a slice of g_logits; (0,0) builds bsum
    if (ch == 0) {
        for (int i = tid; i < (B_ * C_) / F_; i += 256)
            g_logits[f * ((B_ * C_) / F_) + i] = 0.0f;
        if (f == 0 && tid < C_) {
            float s = b_out[tid];
            for (int ff = 0; ff < F_; ff++) s += b2[ff * C_ + tid];
            g_bsum[tid] = s;
        }
    }

    const float* src = W1 + (size_t)f * U_ * V_;
    uint2* dst = g_W1H + ((size_t)f * NCHUNK + ch) * (32 * 512);

    #pragma unroll
    for (int r = 0; r < 64; r++) {
        int idx = r * 256 + tid;           // 0..16383
        int pr = idx >> 9;                 // 0..31
        int v  = idx & 511;
        int s  = pr >> 2, t = pr & 3;
        int ka = ch * KC_ + s * 16 + 2 * t;
        uint2 o;
        o.x = pack_h2(src[(size_t)ka * V_ + v],       src[(size_t)(ka + 1) * V_ + v]);
        o.y = pack_h2(src[(size_t)(ka + 8) * V_ + v], src[(size_t)(ka + 9) * V_ + v]);
        dst[idx] = o;
    }
}

__global__ void nam_dummy_kernel() {}

// ---------------------------------------------------------------------------
// Main GEMM. Grid (16, 4, 128), 256 thr, 8 warps (4 M x 2 N), 2 CTAs/SM.
// The two 128-thread N-groups are fully decoupled in the mainloop:
// each loads its own 16KB B half-slice and syncs on its own named barrier.
// ---------------------------------------------------------------------------
__global__ void __launch_bounds__(256, 2)
nam_gemm_kernel(const float* __restrict__ x,
                const float* __restrict__ exu_w,
                const float* __restrict__ exu_b,
                const float* __restrict__ b1,
                const float* __restrict__ W2) {
    extern __shared__ float sm[];
    uint2*   Bs   = (uint2*)sm;
    __half2* ews2 = (__half2*)(sm + EWS2_OFF);
    float*   xs   = sm + XS_OFF;
    float*   b1s  = sm + B1S_OFF;
    float*   W2s  = sm + W2S_OFF;
    float*   s_part = sm;

    const int f  = blockIdx.z;
    const int b0 = blockIdx.x * BT_;
    const int v0 = blockIdx.y * VT_;
    const int tid = threadIdx.x;
    const int wid = tid >> 5;
    const int lane = tid & 31;
    const int g = lane >> 2;
    const int t = lane & 3;
    const int m0  = (wid & 3) * 32;
    const int nwp = wid >> 2;            // group id (0/1)
    const int n0  = nwp * 64;
    const int tg  = tid & 127;           // thread-in-group

    const uint32_t smem_base = smem_u32(sm);
    const uint2* W1f = g_W1H + ((size_t)f * NCHUNK) * (32 * 512) + v0;

    // prologue: each group loads its half-slice of the first STAGES-1 = 2 chunks
    // group slice: uint2 columns [64*nwp, 64*nwp+64) of each pr row (16KB/chunk)
    #pragma unroll
    for (int pc = 0; pc < STAGES - 1; pc++) {
        #pragma unroll
        for (int it = 0; it < 8; it++) {
            int i = tg + it * 128;               // 0..1023
            int pr = i >> 5;                     // 0..31
            int vc2 = n0 + (i & 31) * 2;
            int tpr = pr & 3;
            int swz2 = (tpr << 3) ^ ((tpr >> 1) << 2);
            uint32_t dst2 = pc * STAGE_U2 + pr * VT_ + (vc2 ^ swz2);
            cpa16(smem_base + dst2 * 8u, W1f + (size_t)pc * (32 * 512) + pr * 512 + vc2);
        }
        CP_COMMIT();
    }

    const float eb = exu_b[f];
    for (int i = tid; i < U_ / 2; i += 256) {
        float2 w = *(const float2*)&exu_w[f * U_ + 2 * i];
        ews2[i] = __floats2half2_rn(expf(w.x), expf(w.y));
    }
    if (tid < BT_) {
        xs[tid]  = x[(size_t)(b0 + tid) * F_ + f] - eb;
        b1s[tid] = b1[(size_t)f * V_ + v0 + tid];
    }
    for (int i = tid; i < VT_ * C_; i += 256) {
        int v = i / C_, c = i - v * C_;
        W2s[v * 12 + c] = W2[(size_t)f * V_ * C_ + (size_t)(v0 + v) * C_ + c];
    }
    __syncthreads();   // tables visible to both groups; groups decouple after this

    __half2 xh[2][2];
    #pragma unroll
    for (int mt = 0; mt < 2; mt++) {
        xh[mt][0] = __half2half2(__float2half_rn(xs[m0 + mt * 16 + g]));
        xh[mt][1] = __half2half2(__float2half_rn(xs[m0 + mt * 16 + g + 8]));
    }

    float acc[2][8][4];
    #pragma unroll
    for (int mt = 0; mt < 2; mt++)
        #pragma unroll
        for (int nt = 0; nt < 8; nt++)
            #pragma unroll
            for (int c = 0; c < 4; c++) acc[mt][nt][c] = 0.0f;

    const int swz = (t << 3) ^ ((t >> 1) << 2);
    int vp[8];
    #pragma unroll
    for (int nt = 0; nt < 8; nt++) vp[nt] = (n0 + nt * 8 + g) ^ swz;

    // ---------------- mainloop: 8 chunks of K=128, group-private sync ----------------
    for (int ch = 0; ch < NCHUNK; ch++) {
        CP_WAIT(1);
        BARG(nwp + 1);                       // only this group's 128 threads
        const uint2* Bst = Bs + (ch % STAGES) * STAGE_U2;
        const int e2b = ch * (KC_ / 2);

        const int nc = ch + STAGES - 1;
        const bool do_load = (nc < NCHUNK);
        const uint32_t ld_stage = (nc % STAGES) * STAGE_U2;
        const uint2* ld_src = W1f + (size_t)(do_load ? nc : 0) * (32 * 512);

        // preload s=0 operands
        uint2 bb[8];
        #pragma unroll
        for (int nt = 0; nt < 8; nt++) bb[nt] = Bst[t * VT_ + vp[nt]];
        __half2 elo = ews2[e2b + t];
        __half2 ehi = ews2[e2b + t + 4];

        #pragma unroll
        for (int s = 0; s < 8; s++) {
            // one group-private cp.async slice per s-step (8 x 128thr x 16B = 16KB)
            if (do_load) {
                int i = tg + s * 128;
                int pr = i >> 5;
                int vc2 = n0 + (i & 31) * 2;
                int tpr = pr & 3;
                int sw2 = (tpr << 3) ^ ((tpr >> 1) << 2);
                uint32_t dst2 = ld_stage + pr * VT_ + (vc2 ^ sw2);
                cpa16(smem_base + dst2 * 8u, ld_src + pr * 512 + vc2);
            }

            uint32_t a[2][4];
            #pragma unroll
            for (int mt = 0; mt < 2; mt++) {
                a[mt][0] = h2u(__hmul2_sat(xh[mt][0], elo));
                a[mt][1] = h2u(__hmul2_sat(xh[mt][1], elo));
                a[mt][2] = h2u(__hmul2_sat(xh[mt][0], ehi));
                a[mt][3] = h2u(__hmul2_sat(xh[mt][1], ehi));
            }
            if (s < 7) {
                elo = ews2[e2b + (s + 1) * 8 + t];
                ehi = ews2[e2b + (s + 1) * 8 + t + 4];
            }
            const int prrow_next = ((s + 1) * 4 + t) * VT_;
            #pragma unroll
            for (int nt = 0; nt < 8; nt++) {
                uint2 bcur = bb[nt];
                if (s < 7) bb[nt] = Bst[prrow_next + vp[nt]];
                mma_f16(acc[0][nt], a[0][0], a[0][1], a[0][2], a[0][3], bcur.x, bcur.y);
                mma_f16(acc[1][nt], a[1][0], a[1][1], a[1][2], a[1][3], bcur.x, bcur.y);
            }
        }
        CP_COMMIT();
    }
    __syncthreads();   // re-converge groups; stage smem reusable as s_part

    // ---------------- epilogue ----------------
    #pragma unroll
    for (int mt = 0; mt < 2; mt++) {
        float p[2][10];
        #pragma unroll
        for (int i = 0; i < 2; i++)
            #pragma unroll
            for (int c = 0; c < 10; c++) p[i][c] = 0.0f;

        #pragma unroll
        for (int nt = 0; nt < 8; nt++) {
            #pragma unroll
            for (int k = 0; k < 2; k++) {
                int vl = n0 + nt * 8 + 2 * t + k;
                float b1v = b1s[vl];
                float w2[10];
                #pragma unroll
                for (int c = 0; c < 10; c++) w2[c] = W2s[vl * 12 + c];
                float h2a = fmaxf(acc[mt][nt][k] + b1v, 0.0f);
                float h2b = fmaxf(acc[mt][nt][2 + k] + b1v, 0.0f);
                #pragma unroll
                for (int c = 0; c < 10; c++) {
                    p[0][c] = fmaf(h2a, w2[c], p[0][c]);
                    p[1][c] = fmaf(h2b, w2[c], p[1][c]);
                }
            }
        }
        #pragma unroll
        for (int off = 1; off < 4; off <<= 1)
            #pragma unroll
            for (int i = 0; i < 2; i++)
                #pragma unroll
                for (int c = 0; c < 10; c++)
                    p[i][c] += __shfl_xor_sync(0xffffffffu, p[i][c], off);

        if (t == 0) {
            #pragma unroll
            for (int rh = 0; rh < 2; rh++) {
                int r = m0 + mt * 16 + g + rh * 8;
                #pragma unroll
                for (int c = 0; c < 10; c++)
                    s_part[(r * 2 + nwp) * 10 + c] = p[rh][c];
            }
        }
    }
    __syncthreads();

    for (int i = tid; i < BT_ * C_; i += 256) {
        int r = i / C_, c = i - r * C_;
        float s = s_part[(r * 2 + 0) * 10 + c] + s_part[(r * 2 + 1) * 10 + c];
        atomicAdd(&g_logits[(b0 + r) * C_ + c], s);
    }
}

// ---------------------------------------------------------------------------
__global__ void nam_softmax_kernel(float* __restrict__ out) {
    int b = blockIdx.x * blockDim.x + threadIdx.x;
    if (b >= B_) return;
    float v[C_];
    float m = -1e30f;
    #pragma unroll
    for (int c = 0; c < C_; c++) {
        v[c] = g_logits[b * C_ + c] + g_bsum[c];
        m = fmaxf(m, v[c]);
    }
    float s = 0.0f;
    #pragma unroll
    for (int c = 0; c < C_; c++) { v[c] = expf(v[c] - m); s += v[c]; }
    float inv = 1.0f / s;
    #pragma unroll
    for (int c = 0; c < C_; c++) out[b * C_ + c] = v[c] * inv;
}

// ---------------------------------------------------------------------------
extern "C" void kernel_launch(void* const* d_in, const int* in_sizes, int n_in,
                              void* d_out, int out_size) {
    const float* x     = (const float*)d_in[0];
    const float* exu_w = (const float*)d_in[1];
    const float* exu_b = (const float*)d_in[2];
    const float* W1    = (const float*)d_in[3];
    const float* b1    = (const float*)d_in[4];
    const float* W2    = (const float*)d_in[5];
    const float* b2    = (const float*)d_in[6];
    const float* b_out = (const float*)d_in[7];
    float* out = (float*)d_out;

    cudaFuncSetAttribute(nam_gemm_kernel,
                         cudaFuncAttributeMaxDynamicSharedMemorySize, SMEM_BYTES);

    dim3 gprep(NCHUNK, F_);
    nam_prep_kernel<<<gprep, 256>>>(W1, b2, b_out);             // launch 0
    nam_dummy_kernel<<<1, 32>>>();                              // launch 1
    nam_dummy_kernel<<<1, 32>>>();                              // launch 2 (ncu align)

    dim3 ggemm(B_ / BT_, V_ / VT_, F_);
    nam_gemm_kernel<<<ggemm, 256, SMEM_BYTES>>>(x, exu_w, exu_b, b1, W2); // launch 3

    nam_softmax_kernel<<<(B_ + 255) / 256, 256>>>(out);         // launch 4
}